// round 14
// baseline (speedup 1.0000x reference)
#include <cuda_runtime.h>
#include <math.h>

#define PI_F 3.14159265358979323846

// Direct bilinear gather, warp-tiled 8x4 (R11 geometry, proven).
// New: x-corner pair loaded as ONE aligned float2 (plus a predicated second
// float2 when x0 is odd) -> ~25% fewer gather instructions / wavefronts.
// Requires W even (guaranteed 8B alignment of row+xe); odd-W uses fallback.

constexpr int BLOCK = 256;

__global__ void __launch_bounds__(BLOCK) affine_warp_tile_f2_kernel(
    const float* __restrict__ x,      // [B, 3, H, W]
    const float* __restrict__ angles, // [B]
    float* __restrict__ out,          // [B, 3, S, S]
    int H, int W, int S, int ntx)
{
    const int b = blockIdx.y;
    const int t = blockIdx.x;
    const int tx = t % ntx;
    const int ty = t / ntx;

    const int tid  = threadIdx.x;
    const int lane = tid & 31;
    const int w    = tid >> 5;

    // warp covers an 8x4 output tile; block = 8 warps = 32x8 region
    const int ox = tx * 32 + (w & 3) * 8 + (lane & 7);
    const int oy = ty * 8  + (w >> 2) * 4 + (lane >> 3);
    if (ox >= S || oy >= S) return;

    // Rotation params (identical arithmetic to reference; per-thread — R12
    // proved compute is not the bottleneck).
    const float rad = angles[b] * (float)(PI_F / 180.0);
    float sn, cs;
    sincosf(rad, &sn, &cs);
    const float scl = fabsf(cs) + fabsf(sn);
    const float c = cs / scl;
    const float s = sn / scl;

    const float step = 2.0f / (float)S;
    const float xs = ((float)ox + 0.5f) * step - 1.0f;
    const float ys = ((float)oy + 0.5f) * step - 1.0f;
    const float gx = c * xs - s * ys;
    const float gy = s * xs + c * ys;
    const float ix = ((gx + 1.0f) * (float)W - 1.0f) * 0.5f;
    const float iy = ((gy + 1.0f) * (float)H - 1.0f) * 0.5f;

    const float x0f = floorf(ix);
    const float y0f = floorf(iy);
    const int x0 = (int)x0f, y0 = (int)y0f;
    const int x1 = x0 + 1,  y1 = y0 + 1;

    const float wx1 = ix - x0f, wx0 = 1.0f - wx1;
    const float wy1 = iy - y0f, wy0 = 1.0f - wy1;

    const bool inx0 = (x0 >= 0) & (x0 < W);
    const bool inx1 = (x1 >= 0) & (x1 < W);
    const bool iny0 = (y0 >= 0) & (y0 < H);
    const bool iny1 = (y1 >= 0) & (y1 < H);

    const float w00 = (inx0 & iny0) ? (wy0 * wx0) : 0.0f;
    const float w01 = (inx1 & iny0) ? (wy0 * wx1) : 0.0f;
    const float w10 = (inx0 & iny1) ? (wy1 * wx0) : 0.0f;
    const float w11 = (inx1 & iny1) ? (wy1 * wx1) : 0.0f;

    const int x0c = min(max(x0, 0), W - 1);
    const int y0c = min(max(y0, 0), H - 1);
    const int y1c = min(max(y1, 0), H - 1);

    // Aligned even base covering x0c (and x1 when x0c even).
    const int  xe   = x0c & ~1;
    const bool odd  = (x0c & 1) != 0;
    // Second pair needed only when x0c odd AND x1 in-bounds (else weight 0).
    const bool needB = odd && inx1;

    const int HW  = H * W;
    const int SSo = S * S;
    const int o0  = y0c * W + xe;   // even offsets -> 8B aligned
    const int o1  = y1c * W + xe;

    const float* img = x + b * 3 * HW;
    float* obase = out + b * 3 * SSo + oy * S + ox;

    #pragma unroll 3
    for (int ch = 0; ch < 3; ++ch) {
        const float* p = img + ch * HW;
        const float2 A0 = __ldg((const float2*)(p + o0));
        const float2 A1 = __ldg((const float2*)(p + o1));
        float2 B0 = make_float2(0.0f, 0.0f);
        float2 B1 = make_float2(0.0f, 0.0f);
        if (needB) {
            B0 = __ldg((const float2*)(p + o0) + 1);
            B1 = __ldg((const float2*)(p + o1) + 1);
        }
        // v00/v10: value at x0c.  v01/v11: value at x1 (don't-care if w==0).
        const float v00 = odd ? A0.y : A0.x;
        const float v10 = odd ? A1.y : A1.x;
        const float v01 = odd ? B0.x : A0.y;
        const float v11 = odd ? B1.x : A1.y;

        float acc = w00 * v00 + w01 * v01 + w10 * v10 + w11 * v11;
        obase[ch * SSo] = acc;
    }
}

// Fallback for odd W (scalar 4-corner gather; R11 kernel).
__global__ void __launch_bounds__(BLOCK) affine_warp_tile_legacy_kernel(
    const float* __restrict__ x, const float* __restrict__ angles,
    float* __restrict__ out, int H, int W, int S, int ntx)
{
    const int b = blockIdx.y;
    const int t = blockIdx.x;
    const int tx = t % ntx;
    const int ty = t / ntx;
    const int tid  = threadIdx.x;
    const int lane = tid & 31;
    const int w    = tid >> 5;
    const int ox = tx * 32 + (w & 3) * 8 + (lane & 7);
    const int oy = ty * 8  + (w >> 2) * 4 + (lane >> 3);
    if (ox >= S || oy >= S) return;

    const float rad = angles[b] * (float)(PI_F / 180.0);
    float sn, cs;
    sincosf(rad, &sn, &cs);
    const float scl = fabsf(cs) + fabsf(sn);
    const float c = cs / scl;
    const float s = sn / scl;

    const float step = 2.0f / (float)S;
    const float xs = ((float)ox + 0.5f) * step - 1.0f;
    const float ys = ((float)oy + 0.5f) * step - 1.0f;
    const float gx = c * xs - s * ys;
    const float gy = s * xs + c * ys;
    const float ix = ((gx + 1.0f) * (float)W - 1.0f) * 0.5f;
    const float iy = ((gy + 1.0f) * (float)H - 1.0f) * 0.5f;

    const float x0f = floorf(ix), y0f = floorf(iy);
    const int x0 = (int)x0f, y0 = (int)y0f, x1 = x0 + 1, y1 = y0 + 1;
    const float wx1 = ix - x0f, wx0 = 1.0f - wx1;
    const float wy1 = iy - y0f, wy0 = 1.0f - wy1;
    const bool inx0 = (x0 >= 0) & (x0 < W), inx1 = (x1 >= 0) & (x1 < W);
    const bool iny0 = (y0 >= 0) & (y0 < H), iny1 = (y1 >= 0) & (y1 < H);
    const float w00 = (inx0 & iny0) ? (wy0 * wx0) : 0.0f;
    const float w01 = (inx1 & iny0) ? (wy0 * wx1) : 0.0f;
    const float w10 = (inx0 & iny1) ? (wy1 * wx0) : 0.0f;
    const float w11 = (inx1 & iny1) ? (wy1 * wx1) : 0.0f;
    const int x0c = min(max(x0, 0), W - 1), x1c = min(max(x1, 0), W - 1);
    const int y0c = min(max(y0, 0), H - 1), y1c = min(max(y1, 0), H - 1);
    const int HW = H * W, SSo = S * S;
    const int i00 = y0c * W + x0c, i01 = y0c * W + x1c;
    const int i10 = y1c * W + x0c, i11 = y1c * W + x1c;
    const float* img = x + b * 3 * HW;
    float* obase = out + b * 3 * SSo + oy * S + ox;
    #pragma unroll 3
    for (int ch = 0; ch < 3; ++ch) {
        const float* p = img + ch * HW;
        float v = w00 * __ldg(p + i00) + w01 * __ldg(p + i01)
                + w10 * __ldg(p + i10) + w11 * __ldg(p + i11);
        obase[ch * SSo] = v;
    }
}

extern "C" void kernel_launch(void* const* d_in, const int* in_sizes, int n_in,
                              void* d_out, int out_size)
{
    const float* x = (const float*)d_in[0];
    const float* angles = (const float*)d_in[1];
    float* out = (float*)d_out;

    const int B = in_sizes[1];
    const int C = 3;
    const long long hw = (long long)in_sizes[0] / ((long long)B * C);
    const int H = (int)(sqrt((double)hw) + 0.5);
    const int W = H;
    const long long ss = (long long)out_size / ((long long)B * C);
    const int S = (int)(sqrt((double)ss) + 0.5);

    const int ntx = (S + 31) / 32;
    const int nty = (S + 7) / 8;
    dim3 grid(ntx * nty, B, 1);

    if ((W & 1) == 0) {
        affine_warp_tile_f2_kernel<<<grid, BLOCK>>>(x, angles, out, H, W, S, ntx);
    } else {
        affine_warp_tile_legacy_kernel<<<grid, BLOCK>>>(x, angles, out, H, W, S, ntx);
    }
}